// round 5
// baseline (speedup 1.0000x reference)
#include <cuda_runtime.h>
#include <math.h>

#define BB 2
#define SS 768
#define DD 1024
#define HH 16
#define HDIM 64
#define NQ 8
#define MROWS (BB*SS)      // 1536
#define BHS (BB*HH*SS)     // 24576

// ---------------- scratch (device globals; no allocations allowed) ----------------
__device__ float g_Q[BB*HH*SS*HDIM];       // [b,h,s,hd]
__device__ float g_K[BB*HH*SS*HDIM];
__device__ float g_V[BB*HH*SS*HDIM];
__device__ float g_u[BHS*16];              // [b,h,s,16] quantum features (Q side, qw folded)
__device__ float g_v[BHS*16];              // (K side)
__device__ float g_P[(size_t)BB*HH*SS*SS]; // scores, then attn probs in-place
__device__ float g_att[BB*SS*DD];          // attended, [b,s,h*64+d] = [B,S,D]
__device__ float g_ent[SS];                // exp(-0.1*|i-j|) lookup

// ---------------- tiny init: entanglement decay table ----------------
__global__ void ent_init_k() {
    int i = threadIdx.x;
    if (i < SS) g_ent[i] = expf(-0.1f * (float)i);
}

// ---------------- fused QKV projection: 128x64x16, double-buffered ----------------
// grid (16, 12, 3): z selects (input, W, bias) and dst among Q/K/V.
// X[1536,1024] @ W[1024,1024] + bias -> permuted [b,h,s,hd]
__global__ __launch_bounds__(256) void projqkv_k(
    const float* __restrict__ q_in, const float* __restrict__ k_in, const float* __restrict__ v_in,
    const float* __restrict__ Wq, const float* __restrict__ Wk, const float* __restrict__ Wv,
    const float* __restrict__ bq, const float* __restrict__ bk, const float* __restrict__ bv)
{
    constexpr int BM = 128, BN = 64, BK = 16;
    __shared__ float As[2][BK][BM + 4];
    __shared__ float Bs[2][BK][BN];

    const int tid = threadIdx.x;
    const int tx = tid & 15, ty = tid >> 4;
    const int m0 = blockIdx.y * BM, n0 = blockIdx.x * BN;
    const int z = blockIdx.z;

    const float* A  = (z == 0) ? q_in : (z == 1) ? k_in : v_in;
    const float* Bm = (z == 0) ? Wq   : (z == 1) ? Wk   : Wv;
    const float* bias = (z == 0) ? bq : (z == 1) ? bk   : bv;
    float* dst = (z == 0) ? g_Q : (z == 1) ? g_K : g_V;
    const int lda = DD, ldb = DD, K = DD;

    const int arow0 = tid >> 2,          akq0 = (tid & 3) << 2;
    const int arow1 = (tid + 256) >> 2,  akq1 = ((tid + 256) & 3) << 2;
    const int br = tid >> 4,             bc = (tid & 15) << 2;

    float4 ra0, ra1, rb;

#define LOADG(kt_) do {                                                             \
        ra0 = *reinterpret_cast<const float4*>(&A[(size_t)(m0 + arow0) * lda + (kt_) + akq0]); \
        ra1 = *reinterpret_cast<const float4*>(&A[(size_t)(m0 + arow1) * lda + (kt_) + akq1]); \
        rb  = *reinterpret_cast<const float4*>(&Bm[(size_t)((kt_) + br) * ldb + n0 + bc]);     \
    } while (0)

#define STOSM(bf_) do {                                                             \
        As[bf_][akq0 + 0][arow0] = ra0.x; As[bf_][akq0 + 1][arow0] = ra0.y;         \
        As[bf_][akq0 + 2][arow0] = ra0.z; As[bf_][akq0 + 3][arow0] = ra0.w;         \
        As[bf_][akq1 + 0][arow1] = ra1.x; As[bf_][akq1 + 1][arow1] = ra1.y;         \
        As[bf_][akq1 + 2][arow1] = ra1.z; As[bf_][akq1 + 3][arow1] = ra1.w;         \
        *reinterpret_cast<float4*>(&Bs[bf_][br][bc]) = rb;                          \
    } while (0)

    float acc[8][4];
    #pragma unroll
    for (int i = 0; i < 8; i++)
        #pragma unroll
        for (int j = 0; j < 4; j++) acc[i][j] = 0.f;

    LOADG(0);
    STOSM(0);
    __syncthreads();

    int cur = 0;
    for (int kt = 0; kt < K; kt += BK) {
        const bool more = (kt + BK) < K;
        if (more) LOADG(kt + BK);

        #pragma unroll
        for (int kk = 0; kk < BK; kk++) {
            float a[8], b[4];
            float4 a0 = *reinterpret_cast<const float4*>(&As[cur][kk][ty * 8]);
            float4 a1 = *reinterpret_cast<const float4*>(&As[cur][kk][ty * 8 + 4]);
            a[0] = a0.x; a[1] = a0.y; a[2] = a0.z; a[3] = a0.w;
            a[4] = a1.x; a[5] = a1.y; a[6] = a1.z; a[7] = a1.w;
            float4 bv4 = *reinterpret_cast<const float4*>(&Bs[cur][kk][tx * 4]);
            b[0] = bv4.x; b[1] = bv4.y; b[2] = bv4.z; b[3] = bv4.w;
            #pragma unroll
            for (int i = 0; i < 8; i++)
                #pragma unroll
                for (int j = 0; j < 4; j++)
                    acc[i][j] += a[i] * b[j];
        }

        if (more) {
            STOSM(cur ^ 1);
            __syncthreads();
            cur ^= 1;
        }
    }
#undef LOADG
#undef STOSM

    #pragma unroll
    for (int i = 0; i < 8; i++) {
        int m = m0 + ty * 8 + i, n = n0 + tx * 4;
        float4 v;
        v.x = acc[i][0] + bias[n];
        v.y = acc[i][1] + bias[n + 1];
        v.z = acc[i][2] + bias[n + 2];
        v.w = acc[i][3] + bias[n + 3];
        int b = m / SS, s = m - b * SS, h = n >> 6, hd = n & 63;
        *reinterpret_cast<float4*>(&dst[((size_t)(b * HH + h) * SS + s) * HDIM + hd]) = v;
    }
}

// ---------------- generic 128x64x16 SGEMM, double-buffered smem ----------------
// mode 1: g_att[1536,1024] @ Wo + bo -> Cout [1536,1024] (row-major)
// mode 2: batched over z=b*16+h: P[768,768] @ V[768,64] -> g_att[b, q, h*64+d]
__global__ __launch_bounds__(256) void sgemm_k(
    const float* __restrict__ Bin,
    const float* __restrict__ bias, float* __restrict__ Cout,
    int mode)
{
    constexpr int BM = 128, BN = 64, BK = 16;
    __shared__ float As[2][BK][BM + 4];
    __shared__ float Bs[2][BK][BN];

    const int tid = threadIdx.x;
    const int tx = tid & 15, ty = tid >> 4;
    const int m0 = blockIdx.y * BM, n0 = blockIdx.x * BN;

    const float* A;
    const float* Bm;
    int lda, ldb, K;
    if (mode == 2) {
        int z = blockIdx.z;
        A = g_P + (size_t)z * SS * SS; lda = SS; K = SS;
        Bm = g_V + (size_t)z * SS * HDIM; ldb = HDIM;
    } else {
        A = g_att; Bm = Bin; lda = DD; ldb = DD; K = DD;
    }

    const int arow0 = tid >> 2,          akq0 = (tid & 3) << 2;
    const int arow1 = (tid + 256) >> 2,  akq1 = ((tid + 256) & 3) << 2;
    const int br = tid >> 4,             bc = (tid & 15) << 2;

    float4 ra0, ra1, rb;

#define LOADG(kt_) do {                                                             \
        ra0 = *reinterpret_cast<const float4*>(&A[(size_t)(m0 + arow0) * lda + (kt_) + akq0]); \
        ra1 = *reinterpret_cast<const float4*>(&A[(size_t)(m0 + arow1) * lda + (kt_) + akq1]); \
        rb  = *reinterpret_cast<const float4*>(&Bm[(size_t)((kt_) + br) * ldb + n0 + bc]);     \
    } while (0)

#define STOSM(bf_) do {                                                             \
        As[bf_][akq0 + 0][arow0] = ra0.x; As[bf_][akq0 + 1][arow0] = ra0.y;         \
        As[bf_][akq0 + 2][arow0] = ra0.z; As[bf_][akq0 + 3][arow0] = ra0.w;         \
        As[bf_][akq1 + 0][arow1] = ra1.x; As[bf_][akq1 + 1][arow1] = ra1.y;         \
        As[bf_][akq1 + 2][arow1] = ra1.z; As[bf_][akq1 + 3][arow1] = ra1.w;         \
        *reinterpret_cast<float4*>(&Bs[bf_][br][bc]) = rb;                          \
    } while (0)

    float acc[8][4];
    #pragma unroll
    for (int i = 0; i < 8; i++)
        #pragma unroll
        for (int j = 0; j < 4; j++) acc[i][j] = 0.f;

    LOADG(0);
    STOSM(0);
    __syncthreads();

    int cur = 0;
    for (int kt = 0; kt < K; kt += BK) {
        const bool more = (kt + BK) < K;
        if (more) LOADG(kt + BK);

        #pragma unroll
        for (int kk = 0; kk < BK; kk++) {
            float a[8], b[4];
            float4 a0 = *reinterpret_cast<const float4*>(&As[cur][kk][ty * 8]);
            float4 a1 = *reinterpret_cast<const float4*>(&As[cur][kk][ty * 8 + 4]);
            a[0] = a0.x; a[1] = a0.y; a[2] = a0.z; a[3] = a0.w;
            a[4] = a1.x; a[5] = a1.y; a[6] = a1.z; a[7] = a1.w;
            float4 bv = *reinterpret_cast<const float4*>(&Bs[cur][kk][tx * 4]);
            b[0] = bv.x; b[1] = bv.y; b[2] = bv.z; b[3] = bv.w;
            #pragma unroll
            for (int i = 0; i < 8; i++)
                #pragma unroll
                for (int j = 0; j < 4; j++)
                    acc[i][j] += a[i] * b[j];
        }

        if (more) {
            STOSM(cur ^ 1);
            __syncthreads();
            cur ^= 1;
        }
    }
#undef LOADG
#undef STOSM

    #pragma unroll
    for (int i = 0; i < 8; i++) {
        int m = m0 + ty * 8 + i, n = n0 + tx * 4;
        float4 v;
        v.x = acc[i][0]; v.y = acc[i][1]; v.z = acc[i][2]; v.w = acc[i][3];
        if (bias) {
            v.x += bias[n]; v.y += bias[n + 1]; v.z += bias[n + 2]; v.w += bias[n + 3];
        }
        if (mode == 1) {
            *reinterpret_cast<float4*>(&Cout[(size_t)m * DD + n]) = v;
        } else {
            int z = blockIdx.z, b = z >> 4, h = z & 15;
            *reinterpret_cast<float4*>(&g_att[(size_t)(b * SS + m) * DD + h * HDIM + n]) = v;
        }
    }
}

// ---------------- quantum feature kernel: rank-16 factorization of cos(a-b) ----------------
__global__ __launch_bounds__(256) void qfeat_k(
    const float* __restrict__ qmapW, const float* __restrict__ qmapb,
    const float* __restrict__ qweights, const float* __restrict__ phasep)
{
    __shared__ float Ws[HDIM * NQ];
    const int tid = threadIdx.x;
    if (tid < HDIM * NQ / 2) {
        ((float2*)Ws)[tid] = ((const float2*)qmapW)[tid];
    }
    __syncthreads();

    const int r = blockIdx.x * 32 + (tid >> 3);   // row in [0, B*H*S)
    const int n = tid & 7;
    const bool isQ = (blockIdx.y == 0);
    const float* row = (isQ ? g_Q : g_K) + (size_t)r * HDIM;
    float s = qmapb[n];
    #pragma unroll 8
    for (int d = 0; d < HDIM; d++) s += row[d] * Ws[d * NQ + n];
    float t = tanhf(s);
    int h = (r / SS) % HH;
    if (isQ) {
        float a = t + phasep[h * NQ + n];
        float qw = 1.f / (1.f + expf(-qweights[h * NQ + n]));
        float sv, cv; sincosf(a, &sv, &cv);
        g_u[(size_t)r * 16 + 2 * n] = qw * cv;
        g_u[(size_t)r * 16 + 2 * n + 1] = qw * sv;
    } else {
        float sv, cv; sincosf(t, &sv, &cv);
        g_v[(size_t)r * 16 + 2 * n] = cv;
        g_v[(size_t)r * 16 + 2 * n + 1] = sv;
    }
}

// ---------------- fused scores: (1-mix)/8 * QK^T + mix/8 * ent * (u.v) ----------------
__global__ __launch_bounds__(256) void scores_k(const float* __restrict__ es_ptr)
{
    __shared__ float Fs[80][65];   // rows 0..63: Q d-dims (transposed); 64..79: u feats
    __shared__ float Gs[80][65];   // K / v
    const int tid = threadIdx.x, tx = tid & 15, ty = tid >> 4;
    const int k0 = blockIdx.x * 64, q0 = blockIdx.y * 64, bh = blockIdx.z;

    const float* Qb = g_Q + (size_t)bh * SS * HDIM;
    const float* Kb = g_K + (size_t)bh * SS * HDIM;
    const float* ub = g_u + (size_t)bh * SS * 16;
    const float* vb = g_v + (size_t)bh * SS * 16;

    #pragma unroll
    for (int i = 0; i < 4; i++) {
        int lin = tid + i * 256;
        int rr = lin >> 4, dq = (lin & 15) << 2;
        float4 a = *reinterpret_cast<const float4*>(&Qb[(size_t)(q0 + rr) * HDIM + dq]);
        Fs[dq + 0][rr] = a.x; Fs[dq + 1][rr] = a.y; Fs[dq + 2][rr] = a.z; Fs[dq + 3][rr] = a.w;
        float4 c = *reinterpret_cast<const float4*>(&Kb[(size_t)(k0 + rr) * HDIM + dq]);
        Gs[dq + 0][rr] = c.x; Gs[dq + 1][rr] = c.y; Gs[dq + 2][rr] = c.z; Gs[dq + 3][rr] = c.w;
    }
    {
        int rr = tid >> 2, nq = (tid & 3) << 2;
        float4 a = *reinterpret_cast<const float4*>(&ub[(size_t)(q0 + rr) * 16 + nq]);
        Fs[64 + nq + 0][rr] = a.x; Fs[64 + nq + 1][rr] = a.y;
        Fs[64 + nq + 2][rr] = a.z; Fs[64 + nq + 3][rr] = a.w;
        float4 c = *reinterpret_cast<const float4*>(&vb[(size_t)(k0 + rr) * 16 + nq]);
        Gs[64 + nq + 0][rr] = c.x; Gs[64 + nq + 1][rr] = c.y;
        Gs[64 + nq + 2][rr] = c.z; Gs[64 + nq + 3][rr] = c.w;
    }
    __syncthreads();

    float acc[4][4], qacc[4][4];
    #pragma unroll
    for (int i = 0; i < 4; i++)
        #pragma unroll
        for (int j = 0; j < 4; j++) { acc[i][j] = 0.f; qacc[i][j] = 0.f; }

    #pragma unroll 8
    for (int kk = 0; kk < 64; kk++) {
        float a[4], b[4];
        #pragma unroll
        for (int i = 0; i < 4; i++) a[i] = Fs[kk][ty * 4 + i];
        #pragma unroll
        for (int j = 0; j < 4; j++) b[j] = Gs[kk][tx * 4 + j];
        #pragma unroll
        for (int i = 0; i < 4; i++)
            #pragma unroll
            for (int j = 0; j < 4; j++)
                acc[i][j] += a[i] * b[j];
    }
    #pragma unroll
    for (int kk = 64; kk < 80; kk++) {
        float a[4], b[4];
        #pragma unroll
        for (int i = 0; i < 4; i++) a[i] = Fs[kk][ty * 4 + i];
        #pragma unroll
        for (int j = 0; j < 4; j++) b[j] = Gs[kk][tx * 4 + j];
        #pragma unroll
        for (int i = 0; i < 4; i++)
            #pragma unroll
            for (int j = 0; j < 4; j++)
                qacc[i][j] += a[i] * b[j];
    }

    float mix = 1.f / (1.f + expf(-es_ptr[0]));
    float c1 = (1.f - mix) * 0.125f;
    float c2 = mix * 0.125f;

    #pragma unroll
    for (int i = 0; i < 4; i++) {
        int q = q0 + ty * 4 + i;
        float4 v;
        #pragma unroll
        for (int j = 0; j < 4; j++) {
            int k = k0 + tx * 4 + j;
            int d = q - k; d = (d < 0) ? -d : d;
            float entv = g_ent[d];
            ((float*)&v)[j] = c1 * acc[i][j] + c2 * entv * qacc[i][j];
        }
        *reinterpret_cast<float4*>(&g_P[((size_t)bh * SS + q) * SS + k0 + tx * 4]) = v;
    }
}

// ---------------- softmax (in-place) + head-mean output ----------------
// Warp shuffle + one cross-warp smem step; 2 barriers per head.
// red[0..7] per-warp maxima, red[8..15] per-warp sums (disjoint slots).
__global__ __launch_bounds__(256) void softmax_k(float* __restrict__ meanout, int wantMean)
{
    __shared__ float red[16];
    const int tid = threadIdx.x;
    const int lane = tid & 31, wid = tid >> 5;
    const int row = blockIdx.x;               // b*S + q
    const int b = row / SS, q = row - b * SS;

    float m0 = 0.f, m1 = 0.f, m2 = 0.f;
    for (int h = 0; h < HH; h++) {
        float* p = g_P + ((size_t)(b * HH + h) * SS + q) * SS;
        float x0 = p[tid], x1 = p[tid + 256], x2 = p[tid + 512];

        float mx = fmaxf(x0, fmaxf(x1, x2));
        #pragma unroll
        for (int o = 16; o > 0; o >>= 1)
            mx = fmaxf(mx, __shfl_xor_sync(0xffffffffu, mx, o));
        if (lane == 0) red[wid] = mx;
        __syncthreads();
        mx = red[0];
        #pragma unroll
        for (int w = 1; w < 8; w++) mx = fmaxf(mx, red[w]);

        float e0 = __expf(x0 - mx), e1 = __expf(x1 - mx), e2 = __expf(x2 - mx);
        float sm = e0 + e1 + e2;
        #pragma unroll
        for (int o = 16; o > 0; o >>= 1)
            sm += __shfl_xor_sync(0xffffffffu, sm, o);
        if (lane == 0) red[8 + wid] = sm;
        __syncthreads();
        sm = red[8];
        #pragma unroll
        for (int w = 1; w < 8; w++) sm += red[8 + w];

        float inv = 1.f / sm;
        e0 *= inv; e1 *= inv; e2 *= inv;
        p[tid] = e0; p[tid + 256] = e1; p[tid + 512] = e2;
        m0 += e0; m1 += e1; m2 += e2;
    }
    if (wantMean) {
        float* o = meanout + (size_t)row * SS;
        const float s = 1.f / (float)HH;
        o[tid] = m0 * s; o[tid + 256] = m1 * s; o[tid + 512] = m2 * s;
    }
}

// ---------------- launch ----------------
extern "C" void kernel_launch(void* const* d_in, const int* in_sizes, int n_in,
                              void* d_out, int out_size)
{
    const float* query = (const float*)d_in[0];
    const float* key   = (const float*)d_in[1];
    const float* value = (const float*)d_in[2];
    const float* Wq = (const float*)d_in[3];  const float* bq = (const float*)d_in[4];
    const float* Wk = (const float*)d_in[5];  const float* bk = (const float*)d_in[6];
    const float* Wv = (const float*)d_in[7];  const float* bv = (const float*)d_in[8];
    const float* Wo = (const float*)d_in[9];  const float* bo = (const float*)d_in[10];
    const float* qmapW = (const float*)d_in[11];
    const float* qmapb = (const float*)d_in[12];
    const float* qwts  = (const float*)d_in[13];
    const float* pp    = (const float*)d_in[14];
    const float* es    = (const float*)d_in[15];
    float* out = (float*)d_out;

    const int OUT0 = BB * SS * DD;                       // 1572864
    const int wantMean = (out_size >= OUT0 + BB * SS * SS) ? 1 : 0;

    ent_init_k<<<1, 768>>>();

    // fused Q/K/V projections: one launch, full chip
    projqkv_k<<<dim3(DD / 64, MROWS / 128, 3), 256>>>(
        query, key, value, Wq, Wk, Wv, bq, bk, bv);

    // quantum features (rank-16 factorization)
    qfeat_k<<<dim3(BHS / 32, 2), 256>>>(qmapW, qmapb, qwts, pp);

    // fused scores
    scores_k<<<dim3(SS / 64, SS / 64, BB * HH), 256>>>(es);

    // softmax in place + head-mean into output tail
    softmax_k<<<BB * SS, 256>>>(out + OUT0, wantMean);

    // attended = P @ V  (batched), written straight into [B,S,D]
    sgemm_k<<<dim3(1, SS / 128, BB * HH), 256>>>(nullptr, nullptr, nullptr, 2);

    // final projection -> out
    sgemm_k<<<dim3(DD / 64, MROWS / 128), 256>>>(Wo, bo, out, 1);
}

// round 7
// speedup vs baseline: 1.0011x; 1.0011x over previous
#include <cuda_runtime.h>
#include <math.h>

#define BB 2
#define SS 768
#define DD 1024
#define HH 16
#define HDIM 64
#define NQ 8
#define MROWS (BB*SS)      // 1536
#define BHS (BB*HH*SS)     // 24576

// ---------------- scratch (device globals; no allocations allowed) ----------------
__device__ float g_Q[BB*HH*SS*HDIM];       // [b,h,s,hd]
__device__ float g_K[BB*HH*SS*HDIM];
__device__ float g_V[BB*HH*SS*HDIM];
__device__ float g_u[BHS*16];              // [b,h,s,16] quantum features (Q side, qw folded)
__device__ float g_v[BHS*16];              // (K side)
__device__ float g_P[(size_t)BB*HH*SS*SS]; // scores, then attn probs in-place
__device__ float g_att[BB*SS*DD];          // attended, [b,s,h*64+d] = [B,S,D]
__device__ float g_ent[SS];                // exp(-0.1*|i-j|) lookup

// ---------------- tiny init: entanglement decay table ----------------
__global__ void ent_init_k() {
    int i = threadIdx.x;
    if (i < SS) g_ent[i] = expf(-0.1f * (float)i);
}

// ---------------- fused QKV projection: 128x64x16, double-buffered ----------------
// grid (16, 12, 3): z selects (input, W, bias) and dst among Q/K/V.
__global__ __launch_bounds__(256) void projqkv_k(
    const float* __restrict__ q_in, const float* __restrict__ k_in, const float* __restrict__ v_in,
    const float* __restrict__ Wq, const float* __restrict__ Wk, const float* __restrict__ Wv,
    const float* __restrict__ bq, const float* __restrict__ bk, const float* __restrict__ bv)
{
    constexpr int BM = 128, BN = 64, BK = 16;
    __shared__ float As[2][BK][BM + 4];
    __shared__ float Bs[2][BK][BN];

    const int tid = threadIdx.x;
    const int tx = tid & 15, ty = tid >> 4;
    const int m0 = blockIdx.y * BM, n0 = blockIdx.x * BN;
    const int z = blockIdx.z;

    const float* A  = (z == 0) ? q_in : (z == 1) ? k_in : v_in;
    const float* Bm = (z == 0) ? Wq   : (z == 1) ? Wk   : Wv;
    const float* bias = (z == 0) ? bq : (z == 1) ? bk   : bv;
    float* dst = (z == 0) ? g_Q : (z == 1) ? g_K : g_V;
    const int lda = DD, ldb = DD, K = DD;

    const int arow0 = tid >> 2,          akq0 = (tid & 3) << 2;
    const int arow1 = (tid + 256) >> 2,  akq1 = ((tid + 256) & 3) << 2;
    const int br = tid >> 4,             bc = (tid & 15) << 2;

    float4 ra0, ra1, rb;

#define LOADG(kt_) do {                                                             \
        ra0 = *reinterpret_cast<const float4*>(&A[(size_t)(m0 + arow0) * lda + (kt_) + akq0]); \
        ra1 = *reinterpret_cast<const float4*>(&A[(size_t)(m0 + arow1) * lda + (kt_) + akq1]); \
        rb  = *reinterpret_cast<const float4*>(&Bm[(size_t)((kt_) + br) * ldb + n0 + bc]);     \
    } while (0)

#define STOSM(bf_) do {                                                             \
        As[bf_][akq0 + 0][arow0] = ra0.x; As[bf_][akq0 + 1][arow0] = ra0.y;         \
        As[bf_][akq0 + 2][arow0] = ra0.z; As[bf_][akq0 + 3][arow0] = ra0.w;         \
        As[bf_][akq1 + 0][arow1] = ra1.x; As[bf_][akq1 + 1][arow1] = ra1.y;         \
        As[bf_][akq1 + 2][arow1] = ra1.z; As[bf_][akq1 + 3][arow1] = ra1.w;         \
        *reinterpret_cast<float4*>(&Bs[bf_][br][bc]) = rb;                          \
    } while (0)

    float acc[8][4];
    #pragma unroll
    for (int i = 0; i < 8; i++)
        #pragma unroll
        for (int j = 0; j < 4; j++) acc[i][j] = 0.f;

    LOADG(0);
    STOSM(0);
    __syncthreads();

    int cur = 0;
    for (int kt = 0; kt < K; kt += BK) {
        const bool more = (kt + BK) < K;
        if (more) LOADG(kt + BK);

        #pragma unroll
        for (int kk = 0; kk < BK; kk++) {
            float a[8], b[4];
            float4 a0 = *reinterpret_cast<const float4*>(&As[cur][kk][ty * 8]);
            float4 a1 = *reinterpret_cast<const float4*>(&As[cur][kk][ty * 8 + 4]);
            a[0] = a0.x; a[1] = a0.y; a[2] = a0.z; a[3] = a0.w;
            a[4] = a1.x; a[5] = a1.y; a[6] = a1.z; a[7] = a1.w;
            float4 bv4 = *reinterpret_cast<const float4*>(&Bs[cur][kk][tx * 4]);
            b[0] = bv4.x; b[1] = bv4.y; b[2] = bv4.z; b[3] = bv4.w;
            #pragma unroll
            for (int i = 0; i < 8; i++)
                #pragma unroll
                for (int j = 0; j < 4; j++)
                    acc[i][j] += a[i] * b[j];
        }

        if (more) {
            STOSM(cur ^ 1);
            __syncthreads();
            cur ^= 1;
        }
    }
#undef LOADG
#undef STOSM

    #pragma unroll
    for (int i = 0; i < 8; i++) {
        int m = m0 + ty * 8 + i, n = n0 + tx * 4;
        float4 v;
        v.x = acc[i][0] + bias[n];
        v.y = acc[i][1] + bias[n + 1];
        v.z = acc[i][2] + bias[n + 2];
        v.w = acc[i][3] + bias[n + 3];
        int b = m / SS, s = m - b * SS, h = n >> 6, hd = n & 63;
        *reinterpret_cast<float4*>(&dst[((size_t)(b * HH + h) * SS + s) * HDIM + hd]) = v;
    }
}

// ---------------- generic 128x64x16 SGEMM, double-buffered smem ----------------
// mode 1: g_att @ Wo + bo -> Cout ; mode 2: batched P @ V -> g_att
__global__ __launch_bounds__(256) void sgemm_k(
    const float* __restrict__ Bin,
    const float* __restrict__ bias, float* __restrict__ Cout,
    int mode)
{
    constexpr int BM = 128, BN = 64, BK = 16;
    __shared__ float As[2][BK][BM + 4];
    __shared__ float Bs[2][BK][BN];

    const int tid = threadIdx.x;
    const int tx = tid & 15, ty = tid >> 4;
    const int m0 = blockIdx.y * BM, n0 = blockIdx.x * BN;

    const float* A;
    const float* Bm;
    int lda, ldb, K;
    if (mode == 2) {
        int z = blockIdx.z;
        A = g_P + (size_t)z * SS * SS; lda = SS; K = SS;
        Bm = g_V + (size_t)z * SS * HDIM; ldb = HDIM;
    } else {
        A = g_att; Bm = Bin; lda = DD; ldb = DD; K = DD;
    }

    const int arow0 = tid >> 2,          akq0 = (tid & 3) << 2;
    const int arow1 = (tid + 256) >> 2,  akq1 = ((tid + 256) & 3) << 2;
    const int br = tid >> 4,             bc = (tid & 15) << 2;

    float4 ra0, ra1, rb;

#define LOADG(kt_) do {                                                             \
        ra0 = *reinterpret_cast<const float4*>(&A[(size_t)(m0 + arow0) * lda + (kt_) + akq0]); \
        ra1 = *reinterpret_cast<const float4*>(&A[(size_t)(m0 + arow1) * lda + (kt_) + akq1]); \
        rb  = *reinterpret_cast<const float4*>(&Bm[(size_t)((kt_) + br) * ldb + n0 + bc]);     \
    } while (0)

#define STOSM(bf_) do {                                                             \
        As[bf_][akq0 + 0][arow0] = ra0.x; As[bf_][akq0 + 1][arow0] = ra0.y;         \
        As[bf_][akq0 + 2][arow0] = ra0.z; As[bf_][akq0 + 3][arow0] = ra0.w;         \
        As[bf_][akq1 + 0][arow1] = ra1.x; As[bf_][akq1 + 1][arow1] = ra1.y;         \
        As[bf_][akq1 + 2][arow1] = ra1.z; As[bf_][akq1 + 3][arow1] = ra1.w;         \
        *reinterpret_cast<float4*>(&Bs[bf_][br][bc]) = rb;                          \
    } while (0)

    float acc[8][4];
    #pragma unroll
    for (int i = 0; i < 8; i++)
        #pragma unroll
        for (int j = 0; j < 4; j++) acc[i][j] = 0.f;

    LOADG(0);
    STOSM(0);
    __syncthreads();

    int cur = 0;
    for (int kt = 0; kt < K; kt += BK) {
        const bool more = (kt + BK) < K;
        if (more) LOADG(kt + BK);

        #pragma unroll
        for (int kk = 0; kk < BK; kk++) {
            float a[8], b[4];
            float4 a0 = *reinterpret_cast<const float4*>(&As[cur][kk][ty * 8]);
            float4 a1 = *reinterpret_cast<const float4*>(&As[cur][kk][ty * 8 + 4]);
            a[0] = a0.x; a[1] = a0.y; a[2] = a0.z; a[3] = a0.w;
            a[4] = a1.x; a[5] = a1.y; a[6] = a1.z; a[7] = a1.w;
            float4 bv = *reinterpret_cast<const float4*>(&Bs[cur][kk][tx * 4]);
            b[0] = bv.x; b[1] = bv.y; b[2] = bv.z; b[3] = bv.w;
            #pragma unroll
            for (int i = 0; i < 8; i++)
                #pragma unroll
                for (int j = 0; j < 4; j++)
                    acc[i][j] += a[i] * b[j];
        }

        if (more) {
            STOSM(cur ^ 1);
            __syncthreads();
            cur ^= 1;
        }
    }
#undef LOADG
#undef STOSM

    #pragma unroll
    for (int i = 0; i < 8; i++) {
        int m = m0 + ty * 8 + i, n = n0 + tx * 4;
        float4 v;
        v.x = acc[i][0]; v.y = acc[i][1]; v.z = acc[i][2]; v.w = acc[i][3];
        if (bias) {
            v.x += bias[n]; v.y += bias[n + 1]; v.z += bias[n + 2]; v.w += bias[n + 3];
        }
        if (mode == 1) {
            *reinterpret_cast<float4*>(&Cout[(size_t)m * DD + n]) = v;
        } else {
            int z = blockIdx.z, b = z >> 4, h = z & 15;
            *reinterpret_cast<float4*>(&g_att[(size_t)(b * SS + m) * DD + h * HDIM + n]) = v;
        }
    }
}

// ---------------- quantum features: rank-16 factorization of cos(a-b) ----------------
__global__ __launch_bounds__(256) void qfeat_k(
    const float* __restrict__ qmapW, const float* __restrict__ qmapb,
    const float* __restrict__ qweights, const float* __restrict__ phasep)
{
    __shared__ float Ws[HDIM * NQ];
    const int tid = threadIdx.x;
    if (tid < HDIM * NQ / 2) {
        ((float2*)Ws)[tid] = ((const float2*)qmapW)[tid];
    }
    __syncthreads();

    const int r = blockIdx.x * 32 + (tid >> 3);
    const int n = tid & 7;
    const bool isQ = (blockIdx.y == 0);
    const float* row = (isQ ? g_Q : g_K) + (size_t)r * HDIM;
    float s = qmapb[n];
    #pragma unroll 8
    for (int d = 0; d < HDIM; d++) s += row[d] * Ws[d * NQ + n];
    float t = tanhf(s);
    int h = (r / SS) % HH;
    if (isQ) {
        float a = t + phasep[h * NQ + n];
        float qw = 1.f / (1.f + expf(-qweights[h * NQ + n]));
        float sv, cv; sincosf(a, &sv, &cv);
        g_u[(size_t)r * 16 + 2 * n] = qw * cv;
        g_u[(size_t)r * 16 + 2 * n + 1] = qw * sv;
    } else {
        float sv, cv; sincosf(t, &sv, &cv);
        g_v[(size_t)r * 16 + 2 * n] = cv;
        g_v[(size_t)r * 16 + 2 * n + 1] = sv;
    }
}

// ---------------- fused scores: (1-mix)/8 * QK^T + mix/8 * ent * (u.v) ----------------
// Rows padded to 68 floats (16B-aligned) -> LDS.128 fragment loads in the hot loop.
__global__ __launch_bounds__(256) void scores_k(const float* __restrict__ es_ptr)
{
    __shared__ __align__(16) float Fs[80][68];   // 0..63: Q dims (transposed); 64..79: u feats
    __shared__ __align__(16) float Gs[80][68];   // K / v
    const int tid = threadIdx.x, tx = tid & 15, ty = tid >> 4;
    const int k0 = blockIdx.x * 64, q0 = blockIdx.y * 64, bh = blockIdx.z;

    const float* Qb = g_Q + (size_t)bh * SS * HDIM;
    const float* Kb = g_K + (size_t)bh * SS * HDIM;
    const float* ub = g_u + (size_t)bh * SS * 16;
    const float* vb = g_v + (size_t)bh * SS * 16;

    #pragma unroll
    for (int i = 0; i < 4; i++) {
        int lin = tid + i * 256;
        int rr = lin >> 4, dq = (lin & 15) << 2;
        float4 a = *reinterpret_cast<const float4*>(&Qb[(size_t)(q0 + rr) * HDIM + dq]);
        Fs[dq + 0][rr] = a.x; Fs[dq + 1][rr] = a.y; Fs[dq + 2][rr] = a.z; Fs[dq + 3][rr] = a.w;
        float4 c = *reinterpret_cast<const float4*>(&Kb[(size_t)(k0 + rr) * HDIM + dq]);
        Gs[dq + 0][rr] = c.x; Gs[dq + 1][rr] = c.y; Gs[dq + 2][rr] = c.z; Gs[dq + 3][rr] = c.w;
    }
    {
        int rr = tid >> 2, nq = (tid & 3) << 2;
        float4 a = *reinterpret_cast<const float4*>(&ub[(size_t)(q0 + rr) * 16 + nq]);
        Fs[64 + nq + 0][rr] = a.x; Fs[64 + nq + 1][rr] = a.y;
        Fs[64 + nq + 2][rr] = a.z; Fs[64 + nq + 3][rr] = a.w;
        float4 c = *reinterpret_cast<const float4*>(&vb[(size_t)(k0 + rr) * 16 + nq]);
        Gs[64 + nq + 0][rr] = c.x; Gs[64 + nq + 1][rr] = c.y;
        Gs[64 + nq + 2][rr] = c.z; Gs[64 + nq + 3][rr] = c.w;
    }
    __syncthreads();

    float acc[4][4], qacc[4][4];
    #pragma unroll
    for (int i = 0; i < 4; i++)
        #pragma unroll
        for (int j = 0; j < 4; j++) { acc[i][j] = 0.f; qacc[i][j] = 0.f; }

    #pragma unroll 8
    for (int kk = 0; kk < 64; kk++) {
        float4 av = *reinterpret_cast<const float4*>(&Fs[kk][ty * 4]);
        float4 bv = *reinterpret_cast<const float4*>(&Gs[kk][tx * 4]);
        float a[4] = {av.x, av.y, av.z, av.w};
        float b[4] = {bv.x, bv.y, bv.z, bv.w};
        #pragma unroll
        for (int i = 0; i < 4; i++)
            #pragma unroll
            for (int j = 0; j < 4; j++)
                acc[i][j] += a[i] * b[j];
    }
    #pragma unroll
    for (int kk = 64; kk < 80; kk++) {
        float4 av = *reinterpret_cast<const float4*>(&Fs[kk][ty * 4]);
        float4 bv = *reinterpret_cast<const float4*>(&Gs[kk][tx * 4]);
        float a[4] = {av.x, av.y, av.z, av.w};
        float b[4] = {bv.x, bv.y, bv.z, bv.w};
        #pragma unroll
        for (int i = 0; i < 4; i++)
            #pragma unroll
            for (int j = 0; j < 4; j++)
                qacc[i][j] += a[i] * b[j];
    }

    float mix = 1.f / (1.f + expf(-es_ptr[0]));
    float c1 = (1.f - mix) * 0.125f;
    float c2 = mix * 0.125f;

    #pragma unroll
    for (int i = 0; i < 4; i++) {
        int q = q0 + ty * 4 + i;
        float4 v;
        #pragma unroll
        for (int j = 0; j < 4; j++) {
            int k = k0 + tx * 4 + j;
            int d = q - k; d = (d < 0) ? -d : d;
            float entv = g_ent[d];
            ((float*)&v)[j] = c1 * acc[i][j] + c2 * entv * qacc[i][j];
        }
        *reinterpret_cast<float4*>(&g_P[((size_t)bh * SS + q) * SS + k0 + tx * 4]) = v;
    }
}

// ---------------- softmax (in-place) + head-mean output ----------------
__global__ __launch_bounds__(256) void softmax_k(float* __restrict__ meanout, int wantMean)
{
    __shared__ float red[16];
    const int tid = threadIdx.x;
    const int lane = tid & 31, wid = tid >> 5;
    const int row = blockIdx.x;
    const int b = row / SS, q = row - b * SS;

    float m0 = 0.f, m1 = 0.f, m2 = 0.f;
    for (int h = 0; h < HH; h++) {
        float* p = g_P + ((size_t)(b * HH + h) * SS + q) * SS;
        float x0 = p[tid], x1 = p[tid + 256], x2 = p[tid + 512];

        float mx = fmaxf(x0, fmaxf(x1, x2));
        #pragma unroll
        for (int o = 16; o > 0; o >>= 1)
            mx = fmaxf(mx, __shfl_xor_sync(0xffffffffu, mx, o));
        if (lane == 0) red[wid] = mx;
        __syncthreads();
        mx = red[0];
        #pragma unroll
        for (int w = 1; w < 8; w++) mx = fmaxf(mx, red[w]);

        float e0 = __expf(x0 - mx), e1 = __expf(x1 - mx), e2 = __expf(x2 - mx);
        float sm = e0 + e1 + e2;
        #pragma unroll
        for (int o = 16; o > 0; o >>= 1)
            sm += __shfl_xor_sync(0xffffffffu, sm, o);
        if (lane == 0) red[8 + wid] = sm;
        __syncthreads();
        sm = red[8];
        #pragma unroll
        for (int w = 1; w < 8; w++) sm += red[8 + w];

        float inv = 1.f / sm;
        e0 *= inv; e1 *= inv; e2 *= inv;
        p[tid] = e0; p[tid + 256] = e1; p[tid + 512] = e2;
        m0 += e0; m1 += e1; m2 += e2;
    }
    if (wantMean) {
        float* o = meanout + (size_t)row * SS;
        const float s = 1.f / (float)HH;
        o[tid] = m0 * s; o[tid + 256] = m1 * s; o[tid + 512] = m2 * s;
    }
}

// ---------------- launch ----------------
extern "C" void kernel_launch(void* const* d_in, const int* in_sizes, int n_in,
                              void* d_out, int out_size)
{
    const float* query = (const float*)d_in[0];
    const float* key   = (const float*)d_in[1];
    const float* value = (const float*)d_in[2];
    const float* Wq = (const float*)d_in[3];  const float* bq = (const float*)d_in[4];
    const float* Wk = (const float*)d_in[5];  const float* bk = (const float*)d_in[6];
    const float* Wv = (const float*)d_in[7];  const float* bv = (const float*)d_in[8];
    const float* Wo = (const float*)d_in[9];  const float* bo = (const float*)d_in[10];
    const float* qmapW = (const float*)d_in[11];
    const float* qmapb = (const float*)d_in[12];
    const float* qwts  = (const float*)d_in[13];
    const float* pp    = (const float*)d_in[14];
    const float* es    = (const float*)d_in[15];
    float* out = (float*)d_out;

    const int OUT0 = BB * SS * DD;
    const int wantMean = (out_size >= OUT0 + BB * SS * SS) ? 1 : 0;

    ent_init_k<<<1, 768>>>();

    // fused Q/K/V projections: one launch, full chip
    projqkv_k<<<dim3(DD / 64, MROWS / 128, 3), 256>>>(
        query, key, value, Wq, Wk, Wv, bq, bk, bv);

    // quantum features
    qfeat_k<<<dim3(BHS / 32, 2), 256>>>(qmapW, qmapb, qwts, pp);

    // fused scores
    scores_k<<<dim3(SS / 64, SS / 64, BB * HH), 256>>>(es);

    // softmax in place + head-mean into output tail
    softmax_k<<<BB * SS, 256>>>(out + OUT0, wantMean);

    // attended = P @ V (batched)
    sgemm_k<<<dim3(1, SS / 128, BB * HH), 256>>>(nullptr, nullptr, nullptr, 2);

    // final projection -> out
    sgemm_k<<<dim3(DD / 64, MROWS / 128), 256>>>(Wo, bo, out, 1);
}